// round 5
// baseline (speedup 1.0000x reference)
#include <cuda_runtime.h>
#include <cuda_fp16.h>
#include <cstdint>

#define NKP 8192
#define KF 256
#define TILES 64                 // 8192/128
#define NCHUNK 12                // 3 product pairs x 4 chunks of K=64
#define STAGEB 32768             // (128+128) rows x 128 B
#define NSTAGE 3

// ---------------- device scratch ----------------
// per matrix: [8192][512] half = [limb0(256) | limb1(256)], prescaled x256
__device__ __align__(16) __half g_A[(size_t)NKP * 512];
__device__ __align__(16) __half g_B[(size_t)NKP * 512];

struct __align__(16) Top2 { float v1; int i1; float v2; int i2; };
__device__ Top2 g_rowPart[(size_t)NKP * TILES];
__device__ Top2 g_colPart[(size_t)NKP * TILES];
__device__ int g_fwd_nn[NKP];
__device__ int g_fwd_ok[NKP];
__device__ int g_bck_nn[NKP];
__device__ int g_bck_ok[NKP];

// ---------------- helpers ----------------
__device__ __forceinline__ void t2_ins(float& v1, int& i1, float& v2, int& i2,
                                       float v, int i) {
    if (v > v1 || (v == v1 && i < i1)) { v2 = v1; i2 = i1; v1 = v; i1 = i; }
    else if (v > v2 || (v == v2 && i < i2)) { v2 = v; i2 = i; }
}

__device__ __forceinline__ void t2_merge_shfl(float& v1, int& i1, float& v2, int& i2,
                                              int delta) {
    float qv1 = __shfl_xor_sync(0xffffffffu, v1, delta);
    int   qi1 = __shfl_xor_sync(0xffffffffu, i1, delta);
    float qv2 = __shfl_xor_sync(0xffffffffu, v2, delta);
    int   qi2 = __shfl_xor_sync(0xffffffffu, i2, delta);
    t2_ins(v1, i1, v2, i2, qv1, qi1);
    t2_ins(v1, i1, v2, i2, qv2, qi2);
}

__device__ __forceinline__ void cp16(void* s, const void* g) {
    unsigned ss = (unsigned)__cvta_generic_to_shared(s);
    asm volatile("cp.async.cg.shared.global [%0], [%1], 16;" :: "r"(ss), "l"(g));
}

__device__ __forceinline__ void mma_f16(float* c, const uint32_t* a, const uint32_t* b) {
    asm volatile(
        "mma.sync.aligned.m16n8k16.row.col.f32.f16.f16.f32 "
        "{%0,%1,%2,%3},{%4,%5,%6,%7},{%8,%9},{%0,%1,%2,%3};"
        : "+f"(c[0]), "+f"(c[1]), "+f"(c[2]), "+f"(c[3])
        : "r"(a[0]), "r"(a[1]), "r"(a[2]), "r"(a[3]), "r"(b[0]), "r"(b[1]));
}

__device__ __forceinline__ void ldsm4(uint32_t& r0, uint32_t& r1,
                                      uint32_t& r2, uint32_t& r3, uint32_t addr) {
    asm volatile("ldmatrix.sync.aligned.m8n8.x4.shared.b16 {%0,%1,%2,%3},[%4];"
                 : "=r"(r0), "=r"(r1), "=r"(r2), "=r"(r3) : "r"(addr));
}

__device__ __forceinline__ uint32_t smem_u32(const void* p) {
    return (uint32_t)__cvta_generic_to_shared(p);
}

// ---------------- split: fp32 -> prescaled 2-limb fp16 --------------------
__global__ void split_kernel(const float* __restrict__ src, int mat)
{
    __half* __restrict__ dst = mat ? g_B : g_A;
    int t = blockIdx.x * blockDim.x + threadIdx.x;
    int n = t & (NKP - 1);
    int kb = t >> 13;                 // 0..31
    if (kb >= KF / 8) return;
    int k0 = kb * 8;

    uint32_t w0[4], w1[4];
#pragma unroll
    for (int p = 0; p < 4; p++) {
        float a = src[(size_t)(k0 + 2 * p) * NKP + n] * 256.0f;
        float b = src[(size_t)(k0 + 2 * p + 1) * NKP + n] * 256.0f;
        __half a0 = __float2half_rn(a), b0 = __float2half_rn(b);
        __half a1 = __float2half_rn(a - __half2float(a0));
        __half b1 = __float2half_rn(b - __half2float(b0));
        __half2 p0 = __halves2half2(a0, b0);
        __half2 p1 = __halves2half2(a1, b1);
        w0[p] = *reinterpret_cast<uint32_t*>(&p0);
        w1[p] = *reinterpret_cast<uint32_t*>(&p1);
    }
    *(uint4*)(dst + (size_t)n * 512 + k0)       = make_uint4(w0[0], w0[1], w0[2], w0[3]);
    *(uint4*)(dst + (size_t)n * 512 + 256 + k0) = make_uint4(w1[0], w1[1], w1[2], w1[3]);
}

// ---------------- GEMM (HMMA + ldmatrix, 3-stage pipe) --------------------
extern __shared__ __align__(1024) char smem[];

__global__ void __launch_bounds__(256, 2)
gemm_hmma()
{
    const int tid = threadIdx.x, wid = tid >> 5, lane = tid & 31;
    const int g = lane >> 2, t = lane & 3;

    // CTA raster swizzle: 8-row bands for L2 locality
    const int gid = blockIdx.y * TILES + blockIdx.x;
    const int band = gid / (TILES * 8);
    const int r_ = gid % (TILES * 8);
    const int by = band * 8 + (r_ & 7);   // row tile (A / descriptors0)
    const int bx = r_ >> 3;               // col tile (B / descriptors1)

    const int wmI = wid & 1, wnI = wid >> 1;
    const int wm = wmI * 64, wn = wnI * 32;

    float s0[4][4][4];
#pragma unroll
    for (int i = 0; i < 4; i++)
#pragma unroll
        for (int j = 0; j < 4; j++)
#pragma unroll
            for (int q = 0; q < 4; q++) s0[i][j][q] = 0.f;

    // product pairs: (A limb, B limb) = (0,0), (0,1), (1,0); K=64 chunks x4 each
    auto prefetch = [&](int q, int stage) {
        int pair = q >> 2, c = q & 3;
        int aOff = (pair == 2) ? 256 : 0;
        int bOff = (pair == 1) ? 256 : 0;
        char* sb = smem + stage * STAGEB;
#pragma unroll
        for (int j = 0; j < 8; j++) {
            int idx = tid + j * 256;       // 0..2047
            int mat = idx >> 10;           // const per j
            int rem = idx & 1023;
            int row = rem >> 3, u = rem & 7;
            const __half* src = mat
                ? g_B + ((size_t)(bx * 128 + row)) * 512 + bOff + c * 64 + u * 8
                : g_A + ((size_t)(by * 128 + row)) * 512 + aOff + c * 64 + u * 8;
            cp16(sb + mat * 16384 + row * 128 + ((u ^ (row & 7)) << 4), src);
        }
        asm volatile("cp.async.commit_group;");
    };

    // per-lane ldmatrix geometry
    const int sub = lane >> 3;
    const int rowoff = (lane & 7) + (sub & 1) * 8;
    const int s2 = sub >> 1;            // k-unit select within k16
    int aRow[4], bRow[2];
#pragma unroll
    for (int mf = 0; mf < 4; mf++) aRow[mf] = wm + mf * 16 + rowoff;
#pragma unroll
    for (int p = 0; p < 2; p++) bRow[p] = wn + p * 16 + rowoff;

    const uint32_t sbu = smem_u32(smem);

    prefetch(0, 0);
    prefetch(1, 1);

    for (int q = 0; q < NCHUNK; q++) {
        if (q + 1 < NCHUNK)
            asm volatile("cp.async.wait_group 1;");
        else
            asm volatile("cp.async.wait_group 0;");
        __syncthreads();
        if (q + 2 < NCHUNK) prefetch(q + 2, (q + 2) % NSTAGE);

        const uint32_t sA_u = sbu + (q % NSTAGE) * STAGEB;
        const uint32_t sB_u = sA_u + 16384;

#pragma unroll
        for (int k16 = 0; k16 < 4; k16++) {
            const int ku = k16 * 2 + s2;
            uint32_t a[4][4], b[4][2];
#pragma unroll
            for (int mf = 0; mf < 4; mf++) {
                int r = aRow[mf];
                ldsm4(a[mf][0], a[mf][1], a[mf][2], a[mf][3],
                      sA_u + r * 128 + ((ku ^ (r & 7)) << 4));
            }
#pragma unroll
            for (int p = 0; p < 2; p++) {
                int r = bRow[p];
                uint32_t r0, r1, r2, r3;
                ldsm4(r0, r1, r2, r3, sB_u + r * 128 + ((ku ^ (r & 7)) << 4));
                b[2 * p][0] = r0; b[2 * p + 1][0] = r1;
                b[2 * p][1] = r2; b[2 * p + 1][1] = r3;
            }
#pragma unroll
            for (int mf = 0; mf < 4; mf++)
#pragma unroll
                for (int nf = 0; nf < 4; nf++)
                    mma_f16(s0[mf][nf], a[mf], b[nf]);
        }
    }

    // undo the x256*x256 prescale
#pragma unroll
    for (int mf = 0; mf < 4; mf++)
#pragma unroll
        for (int nf = 0; nf < 4; nf++)
#pragma unroll
            for (int qq = 0; qq < 4; qq++)
                s0[mf][nf][qq] *= (1.0f / 65536.0f);

    __syncthreads();   // mainloop smem dead; reuse for partials
    Top2* part_row = (Top2*)smem;                   // [128][4]
    Top2* part_col = (Top2*)(smem + 128 * 4 * 16);  // [128][2]

    // ---- row top-2 ----
    {
        float rv1[4][2], rv2[4][2]; int ri1[4][2], ri2[4][2];
#pragma unroll
        for (int mf = 0; mf < 4; mf++)
#pragma unroll
            for (int h = 0; h < 2; h++) {
                rv1[mf][h] = -1e30f; rv2[mf][h] = -1e30f;
                ri1[mf][h] = 0x7fffffff; ri2[mf][h] = 0x7fffffff;
            }
        const int colBase = bx * 128 + wn;
#pragma unroll
        for (int mf = 0; mf < 4; mf++)
#pragma unroll
            for (int nf = 0; nf < 4; nf++)
#pragma unroll
                for (int p = 0; p < 2; p++) {
                    int col = colBase + nf * 8 + t * 2 + p;
                    t2_ins(rv1[mf][0], ri1[mf][0], rv2[mf][0], ri2[mf][0],
                           s0[mf][nf][p], col);
                    t2_ins(rv1[mf][1], ri1[mf][1], rv2[mf][1], ri2[mf][1],
                           s0[mf][nf][p + 2], col);
                }
#pragma unroll
        for (int mf = 0; mf < 4; mf++)
#pragma unroll
            for (int h = 0; h < 2; h++) {
                t2_merge_shfl(rv1[mf][h], ri1[mf][h], rv2[mf][h], ri2[mf][h], 1);
                t2_merge_shfl(rv1[mf][h], ri1[mf][h], rv2[mf][h], ri2[mf][h], 2);
            }
        if (t == 0) {
#pragma unroll
            for (int mf = 0; mf < 4; mf++)
#pragma unroll
                for (int h = 0; h < 2; h++) {
                    int rin = wmI * 64 + mf * 16 + h * 8 + g;
                    Top2 o; o.v1 = rv1[mf][h]; o.i1 = ri1[mf][h];
                    o.v2 = rv2[mf][h]; o.i2 = ri2[mf][h];
                    part_row[rin * 4 + wnI] = o;
                }
        }
    }
    // ---- col top-2 ----
    {
        float cv1[4][2], cv2[4][2]; int ci1[4][2], ci2[4][2];
#pragma unroll
        for (int nf = 0; nf < 4; nf++)
#pragma unroll
            for (int p = 0; p < 2; p++) {
                cv1[nf][p] = -1e30f; cv2[nf][p] = -1e30f;
                ci1[nf][p] = 0x7fffffff; ci2[nf][p] = 0x7fffffff;
            }
        const int rowBase = by * 128 + wm;
#pragma unroll
        for (int nf = 0; nf < 4; nf++)
#pragma unroll
            for (int p = 0; p < 2; p++)
#pragma unroll
                for (int mf = 0; mf < 4; mf++)
#pragma unroll
                    for (int h = 0; h < 2; h++) {
                        int row = rowBase + mf * 16 + h * 8 + g;
                        t2_ins(cv1[nf][p], ci1[nf][p], cv2[nf][p], ci2[nf][p],
                               s0[mf][nf][p + 2 * h], row);
                    }
#pragma unroll
        for (int nf = 0; nf < 4; nf++)
#pragma unroll
            for (int p = 0; p < 2; p++) {
                t2_merge_shfl(cv1[nf][p], ci1[nf][p], cv2[nf][p], ci2[nf][p], 4);
                t2_merge_shfl(cv1[nf][p], ci1[nf][p], cv2[nf][p], ci2[nf][p], 8);
                t2_merge_shfl(cv1[nf][p], ci1[nf][p], cv2[nf][p], ci2[nf][p], 16);
            }
        if (g == 0) {
#pragma unroll
            for (int nf = 0; nf < 4; nf++)
#pragma unroll
                for (int p = 0; p < 2; p++) {
                    int cin = wnI * 32 + nf * 8 + t * 2 + p;
                    Top2 o; o.v1 = cv1[nf][p]; o.i1 = ci1[nf][p];
                    o.v2 = cv2[nf][p]; o.i2 = ci2[nf][p];
                    part_col[cin * 2 + wmI] = o;
                }
        }
    }
    __syncthreads();
    if (tid < 128) {
        float v1 = -1e30f, v2 = -1e30f; int i1 = 0x7fffffff, i2 = 0x7fffffff;
#pragma unroll
        for (int w = 0; w < 4; w++) {
            Top2 q = part_row[tid * 4 + w];
            t2_ins(v1, i1, v2, i2, q.v1, q.i1);
            t2_ins(v1, i1, v2, i2, q.v2, q.i2);
        }
        Top2 o; o.v1 = v1; o.i1 = i1; o.v2 = v2; o.i2 = i2;
        g_rowPart[(size_t)(by * 128 + tid) * TILES + bx] = o;
    } else {
        int col = tid - 128;
        float v1 = -1e30f, v2 = -1e30f; int i1 = 0x7fffffff, i2 = 0x7fffffff;
#pragma unroll
        for (int w = 0; w < 2; w++) {
            Top2 q = part_col[col * 2 + w];
            t2_ins(v1, i1, v2, i2, q.v1, q.i1);
            t2_ins(v1, i1, v2, i2, q.v2, q.i2);
        }
        Top2 o; o.v1 = v1; o.i1 = i1; o.v2 = v2; o.i2 = i2;
        g_colPart[(size_t)(bx * 128 + col) * TILES + by] = o;
    }
}

// ---------------- final reductions ----------------
__global__ void reduce_top2(int which, int tiles, int n)
{
    const Top2* part = which ? g_colPart : g_rowPart;
    int* nn = which ? g_bck_nn : g_fwd_nn;
    int* ok = which ? g_bck_ok : g_fwd_ok;

    int warp = (blockIdx.x * blockDim.x + threadIdx.x) >> 5;
    int lane = threadIdx.x & 31;
    if (warp >= n) return;

    float v1 = -1e30f, v2 = -1e30f; int i1 = 0x7fffffff, i2 = 0x7fffffff;
    for (int p = lane; p < tiles; p += 32) {
        Top2 q = part[(size_t)warp * tiles + p];
        t2_ins(v1, i1, v2, i2, q.v1, q.i1);
        t2_ins(v1, i1, v2, i2, q.v2, q.i2);
    }
    for (int off = 16; off > 0; off >>= 1)
        t2_merge_shfl(v1, i1, v2, i2, off);
    if (lane == 0) {
        float c1 = fmaxf(1.0f - v1, 1e-6f);
        float c2 = fmaxf(1.0f - v2, 1e-6f);
        nn[warp] = i1;
        ok[warp] = (c1 < c2) ? 1 : 0;
    }
}

__global__ void finalize(float* __restrict__ out, int n, int out_size)
{
    int e = blockIdx.x * blockDim.x + threadIdx.x;
    if (e >= out_size) return;
    int seg = e / n, i = e - seg * n;
    float val = 0.0f;
    if (seg == 0 || seg == 2) {
        int j = g_fwd_nn[i];
        bool mutual = g_fwd_ok[i] && g_bck_ok[j] && (g_bck_nn[j] == i);
        int idx = mutual ? j : -1;
        val = (seg == 0) ? (float)idx : ((idx > 0) ? 1.0f : 0.0f);
    } else if (seg == 1) {
        val = -1.0f;
    }
    out[e] = val;
}

extern "C" void kernel_launch(void* const* d_in, const int* in_sizes, int n_in,
                              void* d_out, int out_size)
{
    const float* d0 = (const float*)d_in[0];   // [K, N]
    const float* d1 = (const float*)d_in[1];   // [K, M]
    int N = in_sizes[2] / 2;
    int M = in_sizes[3] / 2;

    cudaFuncSetAttribute(gemm_hmma, cudaFuncAttributeMaxDynamicSharedMemorySize,
                         NSTAGE * STAGEB);

    int splitThreads = NKP * (KF / 8);
    split_kernel<<<splitThreads / 256, 256>>>(d0, 0);
    split_kernel<<<splitThreads / 256, 256>>>(d1, 1);

    dim3 grid(TILES, TILES);
    gemm_hmma<<<grid, 256, NSTAGE * STAGEB>>>();

    reduce_top2<<<(N * 32 + 255) / 256, 256>>>(0, TILES, N);
    reduce_top2<<<(M * 32 + 255) / 256, 256>>>(1, TILES, M);

    finalize<<<(out_size + 255) / 256, 256>>>((float*)d_out, N, out_size);
}

// round 6
// speedup vs baseline: 1.2918x; 1.2918x over previous
#include <cuda_runtime.h>
#include <cuda_fp16.h>
#include <cstdint>

#define NKP 8192
#define KF 256
#define TILES 64                 // 8192/128
#define NCHUNK 4                 // 4 chunks of K=64
#define STAGEB 32768             // (128+128) rows x 128 B
#define PAD 132                  // halves per dtile row (264 B, 8B-aligned)
#define CAND_MAX 64
#define W_THRESH 0.004f

// ---------------- device scratch ----------------
__device__ __align__(16) __half g_Ah[(size_t)NKP * KF];
__device__ __align__(16) __half g_Bh[(size_t)NKP * KF];
__device__ __align__(16) float  g_Af[(size_t)NKP * KF];
__device__ __align__(16) float  g_Bf[(size_t)NKP * KF];
__device__ __align__(16) __half g_dist[(size_t)NKP * NKP];
__device__ __align__(16) __half g_distT[(size_t)NKP * NKP];
__device__ int g_fwd_nn[NKP];
__device__ int g_fwd_ok[NKP];
__device__ int g_bck_nn[NKP];
__device__ int g_bck_ok[NKP];

// ---------------- helpers ----------------
__device__ __forceinline__ void t2_ins(float& v1, int& i1, float& v2, int& i2,
                                       float v, int i) {
    if (v > v1 || (v == v1 && i < i1)) { v2 = v1; i2 = i1; v1 = v; i1 = i; }
    else if (v > v2 || (v == v2 && i < i2)) { v2 = v; i2 = i; }
}

__device__ __forceinline__ void cp16(void* s, const void* g) {
    unsigned ss = (unsigned)__cvta_generic_to_shared(s);
    asm volatile("cp.async.cg.shared.global [%0], [%1], 16;" :: "r"(ss), "l"(g));
}

__device__ __forceinline__ void mma_f16(float* c, const uint32_t* a, const uint32_t* b) {
    asm volatile(
        "mma.sync.aligned.m16n8k16.row.col.f32.f16.f16.f32 "
        "{%0,%1,%2,%3},{%4,%5,%6,%7},{%8,%9},{%0,%1,%2,%3};"
        : "+f"(c[0]), "+f"(c[1]), "+f"(c[2]), "+f"(c[3])
        : "r"(a[0]), "r"(a[1]), "r"(a[2]), "r"(a[3]), "r"(b[0]), "r"(b[1]));
}

__device__ __forceinline__ void ldsm4(uint32_t& r0, uint32_t& r1,
                                      uint32_t& r2, uint32_t& r3, uint32_t addr) {
    asm volatile("ldmatrix.sync.aligned.m8n8.x4.shared.b16 {%0,%1,%2,%3},[%4];"
                 : "=r"(r0), "=r"(r1), "=r"(r2), "=r"(r3) : "r"(addr));
}

__device__ __forceinline__ uint32_t smem_u32(const void* p) {
    return (uint32_t)__cvta_generic_to_shared(p);
}

// ---------------- convert: fp32 [K][N] -> fp16 + fp32 K-major [N][K] -------
__global__ void convert_kernel(const float* __restrict__ src, int mat)
{
    __half* __restrict__ dh = mat ? g_Bh : g_Ah;
    float*  __restrict__ df = mat ? g_Bf : g_Af;
    int t = blockIdx.x * blockDim.x + threadIdx.x;
    int n = t & (NKP - 1);
    int kb = t >> 13;                 // 0..31
    if (kb >= KF / 8) return;
    int k0 = kb * 8;

    float v[8];
#pragma unroll
    for (int i = 0; i < 8; i++) v[i] = src[(size_t)(k0 + i) * NKP + n];

    uint32_t w[4];
#pragma unroll
    for (int p = 0; p < 4; p++) {
        __half2 h = __floats2half2_rn(v[2 * p], v[2 * p + 1]);
        w[p] = *reinterpret_cast<uint32_t*>(&h);
    }
    *(uint4*)(dh + (size_t)n * KF + k0) = make_uint4(w[0], w[1], w[2], w[3]);
    *(float4*)(df + (size_t)n * KF + k0)     = make_float4(v[0], v[1], v[2], v[3]);
    *(float4*)(df + (size_t)n * KF + k0 + 4) = make_float4(v[4], v[5], v[6], v[7]);
}

// ---------------- pass 1: fp16 GEMM, store dist tiles both orientations ---
extern __shared__ __align__(1024) char smem[];

__global__ void __launch_bounds__(256, 2)
gemm_approx()
{
    const int tid = threadIdx.x, wid = tid >> 5, lane = tid & 31;
    const int g = lane >> 2, t = lane & 3;
    const int bx = blockIdx.x;    // col tile (B / descriptors1)
    const int by = blockIdx.y;    // row tile (A / descriptors0)
    const int wmI = wid & 1, wnI = wid >> 1;
    const int wm = wmI * 64, wn = wnI * 32;

    float s0[4][4][4];
#pragma unroll
    for (int i = 0; i < 4; i++)
#pragma unroll
        for (int j = 0; j < 4; j++)
#pragma unroll
            for (int q = 0; q < 4; q++) s0[i][j][q] = 0.f;

    auto prefetch = [&](int c, int stage) {
        char* sb = smem + stage * STAGEB;
#pragma unroll
        for (int j = 0; j < 8; j++) {
            int idx = tid + j * 256;       // 0..2047
            int mat = idx >> 10;
            int rem = idx & 1023;
            int row = rem >> 3, u = rem & 7;
            const __half* src = mat
                ? g_Bh + ((size_t)(bx * 128 + row)) * KF + c * 64 + u * 8
                : g_Ah + ((size_t)(by * 128 + row)) * KF + c * 64 + u * 8;
            cp16(sb + mat * 16384 + row * 128 + ((u ^ (row & 7)) << 4), src);
        }
        asm volatile("cp.async.commit_group;");
    };

    const int sub = lane >> 3;
    const int rowoff = (lane & 7) + (sub & 1) * 8;
    const int s2 = sub >> 1;
    int aRow[4], bRow[2];
#pragma unroll
    for (int mf = 0; mf < 4; mf++) aRow[mf] = wm + mf * 16 + rowoff;
#pragma unroll
    for (int p = 0; p < 2; p++) bRow[p] = wn + p * 16 + rowoff;

    const uint32_t sbu = smem_u32(smem);

    prefetch(0, 0);

    for (int c = 0; c < NCHUNK; c++) {
        const int s = c & 1;
        __syncthreads();
        if (c + 1 < NCHUNK) {
            prefetch(c + 1, s ^ 1);
            asm volatile("cp.async.wait_group 1;");
        } else {
            asm volatile("cp.async.wait_group 0;");
        }
        __syncthreads();

        const uint32_t sA_u = sbu + s * STAGEB;
        const uint32_t sB_u = sA_u + 16384;

#pragma unroll
        for (int k16 = 0; k16 < 4; k16++) {
            const int ku = k16 * 2 + s2;
            uint32_t a[4][4], b[4][2];
#pragma unroll
            for (int mf = 0; mf < 4; mf++) {
                int r = aRow[mf];
                ldsm4(a[mf][0], a[mf][1], a[mf][2], a[mf][3],
                      sA_u + r * 128 + ((ku ^ (r & 7)) << 4));
            }
#pragma unroll
            for (int p = 0; p < 2; p++) {
                int r = bRow[p];
                uint32_t r0, r1, r2, r3;
                ldsm4(r0, r1, r2, r3, sB_u + r * 128 + ((ku ^ (r & 7)) << 4));
                b[2 * p][0] = r0; b[2 * p + 1][0] = r1;
                b[2 * p][1] = r2; b[2 * p + 1][1] = r3;
            }
#pragma unroll
            for (int mf = 0; mf < 4; mf++)
#pragma unroll
                for (int nf = 0; nf < 4; nf++)
                    mma_f16(s0[mf][nf], a[mf], b[nf]);
        }
    }

    // ---- epilogue: tile -> smem fp16 [128][PAD], then both stores ----
    __syncthreads();
    __half* dtile = (__half*)smem;
#pragma unroll
    for (int mf = 0; mf < 4; mf++)
#pragma unroll
        for (int nf = 0; nf < 4; nf++)
#pragma unroll
            for (int h = 0; h < 2; h++) {
                __half2 v2 = __floats2half2_rn(s0[mf][nf][2 * h], s0[mf][nf][2 * h + 1]);
                *(__half2*)&dtile[(size_t)(wm + mf * 16 + h * 8 + g) * PAD
                                  + wn + nf * 8 + t * 2] = v2;
            }
    __syncthreads();

    // (a) row-major store
#pragma unroll
    for (int u = 0; u < 16; u++) {
        int idx = tid + 256 * u;
        int row = idx >> 5, seg = idx & 31;
        uint2 val = *(uint2*)&dtile[row * PAD + seg * 4];
        *(uint2*)(g_dist + ((size_t)(by * 128 + row)) * NKP + bx * 128 + seg * 4) = val;
    }
    // (b) transposed store
#pragma unroll
    for (int u = 0; u < 16; u++) {
        int idx = tid + 256 * u;
        int col = idx >> 5, seg = idx & 31;
        unsigned short h0 = *(unsigned short*)&dtile[(seg * 4 + 0) * PAD + col];
        unsigned short h1 = *(unsigned short*)&dtile[(seg * 4 + 1) * PAD + col];
        unsigned short h2 = *(unsigned short*)&dtile[(seg * 4 + 2) * PAD + col];
        unsigned short h3 = *(unsigned short*)&dtile[(seg * 4 + 3) * PAD + col];
        uint2 val;
        val.x = (uint32_t)h0 | ((uint32_t)h1 << 16);
        val.y = (uint32_t)h2 | ((uint32_t)h3 << 16);
        *(uint2*)(g_distT + ((size_t)(bx * 128 + col)) * NKP + by * 128 + seg * 4) = val;
    }
}

// ---------------- pass 2: scan rows, collect candidates, exact rescore ----
// dist: [8192][8192] fp16 row-major. Arows: fp32 [8192][256] (this side),
// Brows: fp32 [8192][256] (other side). Outputs nn/ok per row.
__global__ void __launch_bounds__(128)
scan_rescore(const __half* __restrict__ dist,
             const float* __restrict__ Arows,
             const float* __restrict__ Brows,
             int* __restrict__ nn, int* __restrict__ ok)
{
    extern __shared__ __align__(16) char ssm[];
    __half* rowbuf = (__half*)ssm;                       // [4][8192]
    float*  abuf   = (float*)(ssm + 4 * NKP * 2);        // [4][256]
    int*    cnt    = (int*)(ssm + 4 * NKP * 2 + 4 * 256 * 4);   // [4]
    int*    cand   = cnt + 4;                            // [4][CAND_MAX]

    const int warp = threadIdx.x >> 5, lane = threadIdx.x & 31;
    const int row = blockIdx.x * 4 + warp;

    // load row into smem
    {
        const uint4* src = (const uint4*)(dist + (size_t)row * NKP);
        uint4* dst = (uint4*)(rowbuf + (size_t)warp * NKP);
#pragma unroll
        for (int u = 0; u < 32; u++) dst[lane + 32 * u] = src[lane + 32 * u];
    }
    // load a-row (fp32, 256)
    {
        const float4* asrc = (const float4*)(Arows + (size_t)row * KF);
        float4* adst = (float4*)(abuf + warp * KF);
        adst[lane] = asrc[lane];
        adst[lane + 32] = asrc[lane + 32];
    }
    if (lane == 0) cnt[warp] = 0;
    __syncwarp();

    const __half* rb = rowbuf + (size_t)warp * NKP;

    // pass A: approx top-2 values
    float v1 = -1e30f, v2 = -1e30f;
#pragma unroll 8
    for (int u = 0; u < 256; u++) {
        float v = __half2float(rb[lane + 32 * u]);
        if (v > v1) { v2 = v1; v1 = v; } else if (v > v2) v2 = v;
    }
#pragma unroll
    for (int off = 16; off > 0; off >>= 1) {
        float q1 = __shfl_xor_sync(0xffffffffu, v1, off);
        float q2 = __shfl_xor_sync(0xffffffffu, v2, off);
        if (q1 > v1) { v2 = fmaxf(v1, q2); v1 = q1; }
        else         { v2 = fmaxf(v2, q1); }
    }
    const float thresh = v2 - W_THRESH;

    // pass B: collect candidate indices
#pragma unroll 8
    for (int u = 0; u < 256; u++) {
        float v = __half2float(rb[lane + 32 * u]);
        if (v >= thresh) {
            int p = atomicAdd(&cnt[warp], 1);
            if (p < CAND_MAX) cand[warp * CAND_MAX + p] = lane + 32 * u;
        }
    }
    __syncwarp();
    int nc = cnt[warp]; if (nc > CAND_MAX) nc = CAND_MAX;

    // exact fp32 rescore of candidates (deterministic fixed tree)
    float ar[8];
#pragma unroll
    for (int m = 0; m < 8; m++) ar[m] = abuf[warp * KF + lane + 32 * m];

    float e1 = -1e30f, e2 = -1e30f; int i1 = 0x7fffffff, i2 = 0x7fffffff;
    for (int c = 0; c < nc; c++) {
        int j = cand[warp * CAND_MAX + c];
        const float* b = Brows + (size_t)j * KF;
        float part = 0.0f;
#pragma unroll
        for (int m = 0; m < 8; m++) part += ar[m] * b[lane + 32 * m];
#pragma unroll
        for (int off = 16; off > 0; off >>= 1)
            part += __shfl_xor_sync(0xffffffffu, part, off);
        t2_ins(e1, i1, e2, i2, part, j);
    }
    if (lane == 0) {
        float c1 = fmaxf(1.0f - e1, 1e-6f);
        float c2 = fmaxf(1.0f - e2, 1e-6f);
        nn[row] = i1;
        ok[row] = (c1 < c2) ? 1 : 0;
    }
}

// ---------------- finalize ----------------
__global__ void finalize(float* __restrict__ out, int n, int out_size)
{
    int e = blockIdx.x * blockDim.x + threadIdx.x;
    if (e >= out_size) return;
    int seg = e / n, i = e - seg * n;
    float val = 0.0f;
    if (seg == 0 || seg == 2) {
        int j = g_fwd_nn[i];
        bool mutual = g_fwd_ok[i] && g_bck_ok[j] && (g_bck_nn[j] == i);
        int idx = mutual ? j : -1;
        val = (seg == 0) ? (float)idx : ((idx > 0) ? 1.0f : 0.0f);
    } else if (seg == 1) {
        val = -1.0f;
    }
    out[e] = val;
}

extern "C" void kernel_launch(void* const* d_in, const int* in_sizes, int n_in,
                              void* d_out, int out_size)
{
    const float* d0 = (const float*)d_in[0];   // [K, N]
    const float* d1 = (const float*)d_in[1];   // [K, M]
    int N = in_sizes[2] / 2;

    static int scan_smem = 4 * NKP * 2 + 4 * 256 * 4 + 16 + 4 * CAND_MAX * 4;

    cudaFuncSetAttribute(gemm_approx, cudaFuncAttributeMaxDynamicSharedMemorySize,
                         2 * STAGEB);
    cudaFuncSetAttribute(scan_rescore, cudaFuncAttributeMaxDynamicSharedMemorySize,
                         scan_smem);

    int convThreads = NKP * (KF / 8);
    convert_kernel<<<convThreads / 256, 256>>>(d0, 0);
    convert_kernel<<<convThreads / 256, 256>>>(d1, 1);

    dim3 grid(TILES, TILES);
    gemm_approx<<<grid, 256, 2 * STAGEB>>>();

    // fwd: rows of dist (A side), rescore vs B
    {
        const __half* dp = g_dist; const float *ap, *bp; int *nnp, *okp;
        cudaMemcpyFromSymbol(&ap, g_Af, 0);   // placeholder, replaced below
    }
    // use device-symbol addresses via kernels directly:
    {
        // obtain raw pointers to __device__ arrays (host-side, not capturable-unsafe)
        void *dist_p, *distT_p, *af_p, *bf_p, *fnn_p, *fok_p, *bnn_p, *bok_p;
        cudaGetSymbolAddress(&dist_p, g_dist);
        cudaGetSymbolAddress(&distT_p, g_distT);
        cudaGetSymbolAddress(&af_p, g_Af);
        cudaGetSymbolAddress(&bf_p, g_Bf);
        cudaGetSymbolAddress(&fnn_p, g_fwd_nn);
        cudaGetSymbolAddress(&fok_p, g_fwd_ok);
        cudaGetSymbolAddress(&bnn_p, g_bck_nn);
        cudaGetSymbolAddress(&bok_p, g_bck_ok);

        scan_rescore<<<NKP / 4, 128, scan_smem>>>(
            (const __half*)dist_p, (const float*)af_p, (const float*)bf_p,
            (int*)fnn_p, (int*)fok_p);
        scan_rescore<<<NKP / 4, 128, scan_smem>>>(
            (const __half*)distT_p, (const float*)bf_p, (const float*)af_p,
            (int*)bnn_p, (int*)bok_p);
    }

    finalize<<<(out_size + 255) / 256, 256>>>((float*)d_out, N, out_size);
}

// round 7
// speedup vs baseline: 1.8203x; 1.4091x over previous
#include <cuda_runtime.h>
#include <cuda_fp16.h>
#include <cstdint>

#define NKP 8192
#define KF 256
#define TILES 64                 // 8192/128
#define NCHUNK 4                 // 4 chunks of K=64
#define STAGEB 32768             // (128+128) rows x 128 B
#define PAD 132                  // halves per dtile row
#define CAND_MAX 64
#define W_THRESH 0.004f

// ---------------- device scratch ----------------
__device__ __align__(16) __half g_Ah[(size_t)NKP * KF];
__device__ __align__(16) __half g_Bh[(size_t)NKP * KF];
__device__ __align__(16) float  g_Af[(size_t)NKP * KF];
__device__ __align__(16) float  g_Bf[(size_t)NKP * KF];
__device__ __align__(16) __half g_dist[(size_t)NKP * NKP];
__device__ __align__(16) __half g_distT[(size_t)NKP * NKP];
__device__ __align__(16) float2 g_rowPartV[(size_t)NKP * TILES];
__device__ __align__(16) float2 g_colPartV[(size_t)NKP * TILES];
__device__ int g_fwd_nn[NKP];
__device__ int g_fwd_ok[NKP];
__device__ int g_bck_nn[NKP];
__device__ int g_bck_ok[NKP];

// ---------------- helpers ----------------
__device__ __forceinline__ void t2_ins(float& v1, int& i1, float& v2, int& i2,
                                       float v, int i) {
    if (v > v1 || (v == v1 && i < i1)) { v2 = v1; i2 = i1; v1 = v; i1 = i; }
    else if (v > v2 || (v == v2 && i < i2)) { v2 = v; i2 = i; }
}

// value-only top-2 insert
__device__ __forceinline__ void v2_ins(float& v1, float& v2, float v) {
    if (v > v1) { v2 = v1; v1 = v; } else if (v > v2) v2 = v;
}
// merge (q1,q2) with q1>=q2 into (v1,v2)
__device__ __forceinline__ void v2_merge(float& v1, float& v2, float q1, float q2) {
    if (q1 > v1) { v2 = fmaxf(v1, q2); v1 = q1; }
    else         { v2 = fmaxf(v2, q1); }
}
__device__ __forceinline__ void v2_merge_shfl(float& v1, float& v2, int delta) {
    float q1 = __shfl_xor_sync(0xffffffffu, v1, delta);
    float q2 = __shfl_xor_sync(0xffffffffu, v2, delta);
    v2_merge(v1, v2, q1, q2);
}

__device__ __forceinline__ void cp16(void* s, const void* g) {
    unsigned ss = (unsigned)__cvta_generic_to_shared(s);
    asm volatile("cp.async.cg.shared.global [%0], [%1], 16;" :: "r"(ss), "l"(g));
}

__device__ __forceinline__ void mma_f16(float* c, const uint32_t* a, const uint32_t* b) {
    asm volatile(
        "mma.sync.aligned.m16n8k16.row.col.f32.f16.f16.f32 "
        "{%0,%1,%2,%3},{%4,%5,%6,%7},{%8,%9},{%0,%1,%2,%3};"
        : "+f"(c[0]), "+f"(c[1]), "+f"(c[2]), "+f"(c[3])
        : "r"(a[0]), "r"(a[1]), "r"(a[2]), "r"(a[3]), "r"(b[0]), "r"(b[1]));
}

__device__ __forceinline__ void ldsm4(uint32_t& r0, uint32_t& r1,
                                      uint32_t& r2, uint32_t& r3, uint32_t addr) {
    asm volatile("ldmatrix.sync.aligned.m8n8.x4.shared.b16 {%0,%1,%2,%3},[%4];"
                 : "=r"(r0), "=r"(r1), "=r"(r2), "=r"(r3) : "r"(addr));
}

__device__ __forceinline__ uint32_t smem_u32(const void* p) {
    return (uint32_t)__cvta_generic_to_shared(p);
}

// ---------------- convert: fp32 [K][N] -> fp16 + fp32 K-major [N][K] -------
__global__ void convert_kernel(const float* __restrict__ src, int mat)
{
    __half* __restrict__ dh = mat ? g_Bh : g_Ah;
    float*  __restrict__ df = mat ? g_Bf : g_Af;
    int t = blockIdx.x * blockDim.x + threadIdx.x;
    int n = t & (NKP - 1);
    int kb = t >> 13;                 // 0..31
    if (kb >= KF / 8) return;
    int k0 = kb * 8;

    float v[8];
#pragma unroll
    for (int i = 0; i < 8; i++) v[i] = src[(size_t)(k0 + i) * NKP + n];

    uint32_t w[4];
#pragma unroll
    for (int p = 0; p < 4; p++) {
        __half2 h = __floats2half2_rn(v[2 * p], v[2 * p + 1]);
        w[p] = *reinterpret_cast<uint32_t*>(&h);
    }
    *(uint4*)(dh + (size_t)n * KF + k0) = make_uint4(w[0], w[1], w[2], w[3]);
    *(float4*)(df + (size_t)n * KF + k0)     = make_float4(v[0], v[1], v[2], v[3]);
    *(float4*)(df + (size_t)n * KF + k0 + 4) = make_float4(v[4], v[5], v[6], v[7]);
}

// ---------------- pass 1: fp16 GEMM; store dist both ways + tile top-2 ----
extern __shared__ __align__(1024) char smem[];

__global__ void __launch_bounds__(256, 2)
gemm_approx()
{
    const int tid = threadIdx.x, wid = tid >> 5, lane = tid & 31;
    const int g = lane >> 2, t = lane & 3;
    const int bx = blockIdx.x;    // col tile (B / descriptors1)
    const int by = blockIdx.y;    // row tile (A / descriptors0)
    const int wmI = wid & 1, wnI = wid >> 1;
    const int wm = wmI * 64, wn = wnI * 32;

    float s0[4][4][4];
#pragma unroll
    for (int i = 0; i < 4; i++)
#pragma unroll
        for (int j = 0; j < 4; j++)
#pragma unroll
            for (int q = 0; q < 4; q++) s0[i][j][q] = 0.f;

    auto prefetch = [&](int c, int stage) {
        char* sb = smem + stage * STAGEB;
#pragma unroll
        for (int j = 0; j < 8; j++) {
            int idx = tid + j * 256;       // 0..2047
            int mat = idx >> 10;
            int rem = idx & 1023;
            int row = rem >> 3, u = rem & 7;
            const __half* src = mat
                ? g_Bh + ((size_t)(bx * 128 + row)) * KF + c * 64 + u * 8
                : g_Ah + ((size_t)(by * 128 + row)) * KF + c * 64 + u * 8;
            cp16(sb + mat * 16384 + row * 128 + ((u ^ (row & 7)) << 4), src);
        }
        asm volatile("cp.async.commit_group;");
    };

    const int sub = lane >> 3;
    const int rowoff = (lane & 7) + (sub & 1) * 8;
    const int s2 = sub >> 1;
    int aRow[4], bRow[2];
#pragma unroll
    for (int mf = 0; mf < 4; mf++) aRow[mf] = wm + mf * 16 + rowoff;
#pragma unroll
    for (int p = 0; p < 2; p++) bRow[p] = wn + p * 16 + rowoff;

    const uint32_t sbu = smem_u32(smem);

    prefetch(0, 0);

    for (int c = 0; c < NCHUNK; c++) {
        const int s = c & 1;
        __syncthreads();
        if (c + 1 < NCHUNK) {
            prefetch(c + 1, s ^ 1);
            asm volatile("cp.async.wait_group 1;");
        } else {
            asm volatile("cp.async.wait_group 0;");
        }
        __syncthreads();

        const uint32_t sA_u = sbu + s * STAGEB;
        const uint32_t sB_u = sA_u + 16384;

#pragma unroll
        for (int k16 = 0; k16 < 4; k16++) {
            const int ku = k16 * 2 + s2;
            uint32_t a[4][4], b[4][2];
#pragma unroll
            for (int mf = 0; mf < 4; mf++) {
                int r = aRow[mf];
                ldsm4(a[mf][0], a[mf][1], a[mf][2], a[mf][3],
                      sA_u + r * 128 + ((ku ^ (r & 7)) << 4));
            }
#pragma unroll
            for (int p = 0; p < 2; p++) {
                int r = bRow[p];
                uint32_t r0, r1, r2, r3;
                ldsm4(r0, r1, r2, r3, sB_u + r * 128 + ((ku ^ (r & 7)) << 4));
                b[2 * p][0] = r0; b[2 * p + 1][0] = r1;
                b[2 * p][1] = r2; b[2 * p + 1][1] = r3;
            }
#pragma unroll
            for (int mf = 0; mf < 4; mf++)
#pragma unroll
                for (int nf = 0; nf < 4; nf++)
                    mma_f16(s0[mf][nf], a[mf], b[nf]);
        }
    }

    // ---- epilogue: stage tile, emit value stores + per-tile top-2 partials
    __syncthreads();
    __half* dtile = (__half*)smem;                              // [128][PAD]
    float2* part_row = (float2*)(smem + 128 * PAD * 2);         // [128][4]
    float2* part_col = (float2*)(smem + 128 * PAD * 2 + 4096);  // [128][2]

#pragma unroll
    for (int mf = 0; mf < 4; mf++)
#pragma unroll
        for (int nf = 0; nf < 4; nf++)
#pragma unroll
            for (int h = 0; h < 2; h++) {
                __half2 v2h = __floats2half2_rn(s0[mf][nf][2 * h], s0[mf][nf][2 * h + 1]);
                *(__half2*)&dtile[(size_t)(wm + mf * 16 + h * 8 + g) * PAD
                                  + wn + nf * 8 + t * 2] = v2h;
            }

    // row top-2 partials (values only)
    {
        float rv1[4][2], rv2[4][2];
#pragma unroll
        for (int mf = 0; mf < 4; mf++)
#pragma unroll
            for (int h = 0; h < 2; h++) { rv1[mf][h] = -1e30f; rv2[mf][h] = -1e30f; }
#pragma unroll
        for (int mf = 0; mf < 4; mf++)
#pragma unroll
            for (int nf = 0; nf < 4; nf++)
#pragma unroll
                for (int p = 0; p < 2; p++) {
                    v2_ins(rv1[mf][0], rv2[mf][0], s0[mf][nf][p]);
                    v2_ins(rv1[mf][1], rv2[mf][1], s0[mf][nf][p + 2]);
                }
#pragma unroll
        for (int mf = 0; mf < 4; mf++)
#pragma unroll
            for (int h = 0; h < 2; h++) {
                v2_merge_shfl(rv1[mf][h], rv2[mf][h], 1);
                v2_merge_shfl(rv1[mf][h], rv2[mf][h], 2);
            }
        if (t == 0) {
#pragma unroll
            for (int mf = 0; mf < 4; mf++)
#pragma unroll
                for (int h = 0; h < 2; h++) {
                    int rin = wmI * 64 + mf * 16 + h * 8 + g;
                    part_row[rin * 4 + wnI] = make_float2(rv1[mf][h], rv2[mf][h]);
                }
        }
    }
    // col top-2 partials
    {
        float cv1[4][2], cv2[4][2];
#pragma unroll
        for (int nf = 0; nf < 4; nf++)
#pragma unroll
            for (int p = 0; p < 2; p++) { cv1[nf][p] = -1e30f; cv2[nf][p] = -1e30f; }
#pragma unroll
        for (int nf = 0; nf < 4; nf++)
#pragma unroll
            for (int p = 0; p < 2; p++)
#pragma unroll
                for (int mf = 0; mf < 4; mf++)
#pragma unroll
                    for (int h = 0; h < 2; h++)
                        v2_ins(cv1[nf][p], cv2[nf][p], s0[mf][nf][p + 2 * h]);
#pragma unroll
        for (int nf = 0; nf < 4; nf++)
#pragma unroll
            for (int p = 0; p < 2; p++) {
                v2_merge_shfl(cv1[nf][p], cv2[nf][p], 4);
                v2_merge_shfl(cv1[nf][p], cv2[nf][p], 8);
                v2_merge_shfl(cv1[nf][p], cv2[nf][p], 16);
            }
        if (g == 0) {
#pragma unroll
            for (int nf = 0; nf < 4; nf++)
#pragma unroll
                for (int p = 0; p < 2; p++) {
                    int cin = wnI * 32 + nf * 8 + t * 2 + p;
                    part_col[cin * 2 + wmI] = make_float2(cv1[nf][p], cv2[nf][p]);
                }
        }
    }
    __syncthreads();

    // (a) row-major store
#pragma unroll
    for (int u = 0; u < 16; u++) {
        int idx = tid + 256 * u;
        int row = idx >> 5, seg = idx & 31;
        uint2 val = *(uint2*)&dtile[row * PAD + seg * 4];
        *(uint2*)(g_dist + ((size_t)(by * 128 + row)) * NKP + bx * 128 + seg * 4) = val;
    }
    // (b) transposed store
#pragma unroll
    for (int u = 0; u < 16; u++) {
        int idx = tid + 256 * u;
        int col = idx >> 5, seg = idx & 31;
        unsigned short h0 = *(unsigned short*)&dtile[(seg * 4 + 0) * PAD + col];
        unsigned short h1 = *(unsigned short*)&dtile[(seg * 4 + 1) * PAD + col];
        unsigned short h2 = *(unsigned short*)&dtile[(seg * 4 + 2) * PAD + col];
        unsigned short h3 = *(unsigned short*)&dtile[(seg * 4 + 3) * PAD + col];
        uint2 val;
        val.x = (uint32_t)h0 | ((uint32_t)h1 << 16);
        val.y = (uint32_t)h2 | ((uint32_t)h3 << 16);
        *(uint2*)(g_distT + ((size_t)(bx * 128 + col)) * NKP + by * 128 + seg * 4) = val;
    }
    // (c) reduce partials, store global per-tile top-2 values
    if (tid < 128) {
        float v1 = -1e30f, v2 = -1e30f;
#pragma unroll
        for (int w = 0; w < 4; w++) {
            float2 q = part_row[tid * 4 + w];
            v2_merge(v1, v2, q.x, q.y);
        }
        g_rowPartV[(size_t)(by * 128 + tid) * TILES + bx] = make_float2(v1, v2);
    } else {
        int col = tid - 128;
        float v1 = -1e30f, v2 = -1e30f;
#pragma unroll
        for (int w = 0; w < 2; w++) {
            float2 q = part_col[col * 2 + w];
            v2_merge(v1, v2, q.x, q.y);
        }
        g_colPartV[(size_t)(bx * 128 + col) * TILES + by] = make_float2(v1, v2);
    }
}

// ---------------- pass 2: tile-pruned candidate scan + exact rescore ------
__global__ void __launch_bounds__(256)
scan2(const __half* __restrict__ dist, const float2* __restrict__ partV,
      const float* __restrict__ Arows, const float* __restrict__ Brows,
      int* __restrict__ nn, int* __restrict__ ok)
{
    __shared__ int cnt[8];
    __shared__ int cand[8][CAND_MAX];
    const int warp = threadIdx.x >> 5, lane = threadIdx.x & 31;
    const int row = blockIdx.x * 8 + warp;

    // reduce 64 per-tile (v1,v2) partials to global approx top-2
    float2 p0 = partV[(size_t)row * TILES + lane];
    float2 p1 = partV[(size_t)row * TILES + 32 + lane];
    float v1, v2;
    if (p0.x > p1.x) { v1 = p0.x; v2 = fmaxf(p0.y, p1.x); }
    else             { v1 = p1.x; v2 = fmaxf(p1.y, p0.x); }
#pragma unroll
    for (int off = 16; off > 0; off >>= 1)
        v2_merge_shfl(v1, v2, off);
    const float t = v2 - W_THRESH;

    if (lane == 0) cnt[warp] = 0;
    __syncwarp();

    // tiles that can contain candidates
    unsigned m0 = __ballot_sync(0xffffffffu, p0.x >= t);
    unsigned m1 = __ballot_sync(0xffffffffu, p1.x >= t);

    const __half* rb = dist + (size_t)row * NKP;
    while (m0 | m1) {
        int p;
        if (m0) { p = __ffs(m0) - 1; m0 &= m0 - 1; }
        else    { p = 32 + __ffs(m1) - 1; m1 &= m1 - 1; }
        uint2 val = *(const uint2*)(rb + p * 128 + lane * 4);
        __half2 h01 = *(__half2*)&val.x;
        __half2 h23 = *(__half2*)&val.y;
        float f[4] = { __low2float(h01), __high2float(h01),
                       __low2float(h23), __high2float(h23) };
#pragma unroll
        for (int k = 0; k < 4; k++)
            if (f[k] >= t) {
                int q = atomicAdd(&cnt[warp], 1);
                if (q < CAND_MAX) cand[warp][q] = p * 128 + lane * 4 + k;
            }
    }
    __syncwarp();
    int nc = cnt[warp]; if (nc > CAND_MAX) nc = CAND_MAX;

    // exact fp32 rescore (deterministic fixed tree, same both directions)
    float ar[8];
#pragma unroll
    for (int m = 0; m < 8; m++) ar[m] = Arows[(size_t)row * KF + lane + 32 * m];

    float e1 = -1e30f, e2 = -1e30f; int i1 = 0x7fffffff, i2 = 0x7fffffff;
    for (int c = 0; c < nc; c++) {
        int j = cand[warp][c];
        const float* b = Brows + (size_t)j * KF;
        float part = 0.0f;
#pragma unroll
        for (int m = 0; m < 8; m++) part = fmaf(ar[m], b[lane + 32 * m], part);
#pragma unroll
        for (int off = 16; off > 0; off >>= 1)
            part += __shfl_xor_sync(0xffffffffu, part, off);
        t2_ins(e1, i1, e2, i2, part, j);
    }
    if (lane == 0) {
        float c1 = fmaxf(1.0f - e1, 1e-6f);
        float c2 = fmaxf(1.0f - e2, 1e-6f);
        nn[row] = i1;
        ok[row] = (c1 < c2) ? 1 : 0;
    }
}

// ---------------- finalize ----------------
__global__ void finalize(float* __restrict__ out, int n, int out_size)
{
    int e = blockIdx.x * blockDim.x + threadIdx.x;
    if (e >= out_size) return;
    int seg = e / n, i = e - seg * n;
    float val = 0.0f;
    if (seg == 0 || seg == 2) {
        int j = g_fwd_nn[i];
        bool mutual = g_fwd_ok[i] && g_bck_ok[j] && (g_bck_nn[j] == i);
        int idx = mutual ? j : -1;
        val = (seg == 0) ? (float)idx : ((idx > 0) ? 1.0f : 0.0f);
    } else if (seg == 1) {
        val = -1.0f;
    }
    out[e] = val;
}

extern "C" void kernel_launch(void* const* d_in, const int* in_sizes, int n_in,
                              void* d_out, int out_size)
{
    const float* d0 = (const float*)d_in[0];   // [K, N]
    const float* d1 = (const float*)d_in[1];   // [K, M]
    int N = in_sizes[2] / 2;

    cudaFuncSetAttribute(gemm_approx, cudaFuncAttributeMaxDynamicSharedMemorySize,
                         2 * STAGEB);

    int convThreads = NKP * (KF / 8);
    convert_kernel<<<convThreads / 256, 256>>>(d0, 0);
    convert_kernel<<<convThreads / 256, 256>>>(d1, 1);

    dim3 grid(TILES, TILES);
    gemm_approx<<<grid, 256, 2 * STAGEB>>>();

    void *dist_p, *distT_p, *af_p, *bf_p, *rp_p, *cp_p;
    void *fnn_p, *fok_p, *bnn_p, *bok_p;
    cudaGetSymbolAddress(&dist_p, g_dist);
    cudaGetSymbolAddress(&distT_p, g_distT);
    cudaGetSymbolAddress(&af_p, g_Af);
    cudaGetSymbolAddress(&bf_p, g_Bf);
    cudaGetSymbolAddress(&rp_p, g_rowPartV);
    cudaGetSymbolAddress(&cp_p, g_colPartV);
    cudaGetSymbolAddress(&fnn_p, g_fwd_nn);
    cudaGetSymbolAddress(&fok_p, g_fwd_ok);
    cudaGetSymbolAddress(&bnn_p, g_bck_nn);
    cudaGetSymbolAddress(&bok_p, g_bck_ok);

    scan2<<<NKP / 8, 256>>>((const __half*)dist_p, (const float2*)rp_p,
                            (const float*)af_p, (const float*)bf_p,
                            (int*)fnn_p, (int*)fok_p);
    scan2<<<NKP / 8, 256>>>((const __half*)distT_p, (const float2*)cp_p,
                            (const float*)bf_p, (const float*)af_p,
                            (int*)bnn_p, (int*)bok_p);

    finalize<<<(out_size + 255) / 256, 256>>>((float*)d_out, N, out_size);
}